// round 13
// baseline (speedup 1.0000x reference)
#include <cuda_runtime.h>

#define NL     32
#define NF     720
#define NSUB   60
#define DTF    60.0f
#define SCALE  256.0f
#define CLM    45          // modal chunk length (16 warps: 15*45 + 44 = 719)
#define NCHM   16
#define TBLK   512
#define GRID1  46          // block 0 = modal, blocks 1..45 = transform

typedef unsigned long long u64;
#define FULL 0xffffffffu

// Persistent scratch (zero-initialized at module load)
__device__ float    g_A  [NL * NL];
__device__ float2   g_Lam[NL];
__device__ float2   g_G0 [NL];
__device__ float2   g_G1 [NL];
__device__ float2   g_Z  [NF * NL];
__device__ unsigned g_gen[GRID1];    // per-block epoch tickets
__device__ unsigned g_cnt;           // eigen arrivals (monotonic)
__device__ unsigned g_flag;          // modal-done generation (monotonic)

// ---- packed f32x2 helpers ---------------------------------------------------
__device__ __forceinline__ u64 pk2(float lo, float hi) {
    u64 r; asm("mov.b64 %0, {%1, %2};" : "=l"(r) : "f"(lo), "f"(hi)); return r;
}
__device__ __forceinline__ void upk2(float& lo, float& hi, u64 v) {
    asm("mov.b64 {%0, %1}, %2;" : "=f"(lo), "=f"(hi) : "l"(v));
}
__device__ __forceinline__ void ffma2(u64& d, u64 a, u64 b) {
    asm("fma.rn.f32x2 %0, %1, %2, %3;" : "=l"(d) : "l"(a), "l"(b), "l"(d));
}
__device__ __forceinline__ float frcpa(float x) {
    float r; asm("rcp.approx.f32 %0, %1;" : "=f"(r) : "f"(x)); return r;
}
__device__ __forceinline__ float2 cmulf(float2 a, float2 b) {
    return make_float2(a.x * b.x - a.y * b.y, a.x * b.y + a.y * b.x);
}
__device__ __forceinline__ void cdmul(double& zr, double& zi, double ar, double ai) {
    double tr = zr * ar - zi * ai;
    zi = zr * ai + zi * ar;
    zr = tr;
}

// Sturm count
__device__ __forceinline__ int sturm_count(float x,
                                           const float* __restrict__ ch,
                                           const float* __restrict__ s2h)
{
    float p0 = 1.0f;
    float p1 = ch[0] - x;
    bool  s1 = (p1 < 0.0f) || (p1 == 0.0f);
    int   cnt = s1 ? 1 : 0;
    #pragma unroll
    for (int r = 1; r < NL; ++r) {
        float p2 = fmaf(ch[r] - x, p1, -s2h[r] * p0);
        bool sg = (p2 < 0.0f);
        if (p2 == 0.0f) sg = !s1;
        cnt += (sg != s1) ? 1 : 0;
        float ap = fabsf(p2);
        float sc = 1.0f;
        if (ap > 1e18f) sc = 1e-18f;
        else if (ap < 1e-18f) sc = 1e18f;
        p0 = p1 * sc;
        p1 = p2 * sc;
        s1 = sg;
    }
    return cnt;
}

// ---------------------------------------------------------------------------
// THE kernel. 46 blocks x 512 threads, all phases internal.
// ---------------------------------------------------------------------------
__global__ void __launch_bounds__(TBLK, 1)
mega_kernel(const float* __restrict__ pk,  const float* __restrict__ fc,
            const float* __restrict__ TAx, const float* __restrict__ TAy,
            float* __restrict__ out)
{
    // eigen-phase smem
    __shared__ float ch [NL];
    __shared__ float sh [NL];
    __shared__ float s2h[NL];
    __shared__ float vsm[NL];
    // modal-phase smem (block 0)
    __shared__ float2 zloc[NCHM][NL];
    __shared__ float2 carr[NCHM][NL];
    // transform-phase smem (blocks 1..45)
    __shared__ float  As[NL * NL];
    __shared__ float2 Zs[16 * NL];
    __shared__ unsigned e_sm;

    const int tid = threadIdx.x;
    const int b   = blockIdx.x;

    // ---- epoch ticket (replay-safe rendezvous) ----
    if (tid == 0) e_sm = atomicAdd(&g_gen[b], 1u) + 1u;
    __syncthreads();
    const unsigned e = e_sm;

    // =======================================================================
    // Phase E: eigen solve for mode b (blocks 0..31, warp 0 only)
    // =======================================================================
    if (b < NL && tid < 32) {
        const int lane = tid;
        const int l    = b;

        const float kin  = expf(pk[2 * lane]);
        const float kout = expf(pk[2 * lane + 1]);
        const float fc0  = fc[0];

        // symmetrizer
        float t = (lane > 0) ? 0.5f * (pk[2 * lane - 1] - pk[2 * lane]) : 0.0f;
        #pragma unroll
        for (int o = 1; o < 32; o <<= 1) {
            float u = __shfl_up_sync(FULL, t, o);
            if (lane >= o) t += u;
        }
        const float dinv = expf(-t);

        const float c = -DTF * (((lane > 0) ? kin : 0.0f) + kout) * SCALE;
        const float s = (lane > 0)
            ? DTF * expf(0.5f * (pk[2 * lane] + pk[2 * lane - 1])) * SCALE
            : 0.0f;
        ch[lane]  = c;
        sh[lane]  = s;
        s2h[lane] = s * s;
        const float s_up = __shfl_down_sync(FULL, s, 1);
        const float offp = (lane < NL - 1) ? s_up : 0.0f;
        __syncwarp();

        // Gershgorin
        float rad = s + offp;
        float lo  = c - rad, hi = c + rad;
        #pragma unroll
        for (int o = 16; o > 0; o >>= 1) {
            lo = fminf(lo, __shfl_xor_sync(FULL, lo, o));
            hi = fmaxf(hi, __shfl_xor_sync(FULL, hi, o));
        }
        float width = hi - lo;
        float a_ = lo - 1e-6f * (fabsf(width) + 1.0f);
        float b_ = hi + 1e-6f * (fabsf(width) + 1.0f);

        // 32-point bisection, 5 rounds
        for (int round = 0; round < 5; ++round) {
            float x = a_ + (b_ - a_) * (float)(lane + 1) * (1.0f / 33.0f);
            int cnt = sturm_count(x, ch, s2h);
            unsigned mask = __ballot_sync(FULL, cnt <= l);
            if (mask) {
                int j = 31 - __clz((int)mask);
                float na = __shfl_sync(FULL, x, j);
                float nb = (j < 31) ? __shfl_sync(FULL, x, j + 1) : b_;
                a_ = na; b_ = nb;
            } else {
                b_ = __shfl_sync(FULL, x, 0);
            }
        }
        const float xhat = 0.5f * (a_ + b_);

        // divergent overlap: Thomas (lane 31)  ||  fp64 tail (lanes 0..30)
        double g0r = 0.0, g0i = 0.0, g1r = 0.0, g1i = 0.0;
        double Lr  = 0.0, Li  = 0.0;

        if (lane == 31) {
            float rp[NL];
            {
                float dd = ch[0] - xhat;
                dd = copysignf(fmaxf(fabsf(dd), 1e-12f), dd);
                rp[0] = frcpa(dd);
                #pragma unroll
                for (int r = 1; r < NL; ++r) {
                    dd = fmaf(-s2h[r], rp[r - 1], ch[r] - xhat);
                    dd = copysignf(fmaxf(fabsf(dd), 1e-12f), dd);
                    rp[r] = frcpa(dd);
                }
            }
            float vb[NL];
            #pragma unroll
            for (int r = 0; r < NL; ++r) vb[r] = 1.0f;

            #pragma unroll
            for (int it = 0; it < 3; ++it) {
                float wk[NL];
                wk[0] = vb[0];
                #pragma unroll
                for (int r = 1; r < NL; ++r) {
                    float m = sh[r] * rp[r - 1];
                    wk[r] = fmaf(-m, wk[r - 1], vb[r]);
                }
                wk[NL - 1] = wk[NL - 1] * rp[NL - 1];
                #pragma unroll
                for (int r = NL - 2; r >= 0; --r)
                    wk[r] = (wk[r] - sh[r + 1] * wk[r + 1]) * rp[r];

                float n2 = 0.0f;
                #pragma unroll
                for (int r = 0; r < NL; ++r) n2 += wk[r] * wk[r];
                float inv = rsqrtf(n2);
                #pragma unroll
                for (int r = 0; r < NL; ++r) vb[r] = wk[r] * inv;
            }
            #pragma unroll
            for (int r = 0; r < NL; ++r) vsm[r] = vb[r];
        } else {
            const double mu = (double)xhat / (double)SCALE;
            const double br = 1.0 + mu;
            const double bi = -(double)DTF * (double)fc0;

            double sqr_r[6], sqr_i[6];
            sqr_r[0] = br; sqr_i[0] = bi;
            #pragma unroll
            for (int k = 1; k < 6; ++k) {
                double rr = sqr_r[k-1], ii = sqr_i[k-1];
                sqr_r[k] = rr * rr - ii * ii;
                sqr_i[k] = 2.0 * rr * ii;
            }

            const int e1 = 59 - lane;
            const int e2 = 28 - lane;
            double p1r = 1.0, p1i = 0.0, p2r = 1.0, p2i = 0.0;
            #pragma unroll
            for (int k = 0; k < 6; ++k) {
                if (e1 & (1 << k)) cdmul(p1r, p1i, sqr_r[k], sqr_i[k]);
                if (e2 >= 0 && (e2 & (1 << k))) cdmul(p2r, p2i, sqr_r[k], sqr_i[k]);
            }

            const double w2a = (double)lane * (1.0 / 60.0),        w1a = 1.0 - w2a;
            const double w2b = (double)(lane + 31) * (1.0 / 60.0), w1b = 1.0 - w2b;
            const bool   hb  = (e2 >= 0);
            g0r = w1a * p1r + (hb ? w1b * p2r : 0.0);
            g0i = w1a * p1i + (hb ? w1b * p2i : 0.0);
            g1r = w2a * p1r + (hb ? w2b * p2r : 0.0);
            g1i = w2a * p1i + (hb ? w2b * p2i : 0.0);

            Lr = sqr_r[5]; Li = sqr_i[5];
            cdmul(Lr, Li, sqr_r[4], sqr_i[4]);
            cdmul(Lr, Li, sqr_r[3], sqr_i[3]);
            cdmul(Lr, Li, sqr_r[2], sqr_i[2]);
        }
        __syncwarp();

        #pragma unroll
        for (int o = 16; o > 0; o >>= 1) {
            g0r += __shfl_xor_sync(FULL, g0r, o);
            g0i += __shfl_xor_sync(FULL, g0i, o);
            g1r += __shfl_xor_sync(FULL, g1r, o);
            g1i += __shfl_xor_sync(FULL, g1i, o);
        }

        g_A[l * NL + lane] = vsm[lane] * dinv;

        if (lane == 0) {
            const double sc = (double)DTF * (double)expf(pk[0]) * (double)vsm[0];
            g_Lam[l] = make_float2((float)Lr, (float)Li);
            g_G0[l]  = make_float2((float)(sc * g0r), (float)(sc * g0i));
            g_G1[l]  = make_float2((float)(sc * g1r), (float)(sc * g1i));
        }
        __threadfence();
        if (lane == 0) atomicAdd(&g_cnt, 1u);
    }

    // =======================================================================
    // Phase M (block 0): modal scan, all 512 threads
    // =======================================================================
    if (b == 0) {
        if (tid == 0)
            while (atomicAdd(&g_cnt, 0u) < 32u * e) __nanosleep(32);
        __syncthreads();
        __threadfence();

        const int l = tid & 31;
        const int c = tid >> 5;

        const float2 L  = g_Lam[l];
        const float2 G0 = g_G0[l];
        const float2 G1 = g_G1[l];

        const int k0  = c * CLM;
        const int len = min(CLM, (NF - 1) - k0);

        float zr = 0.0f, zi = 0.0f;
        for (int m = 0; m < len; ++m) {
            const int k = k0 + m;
            float txa = TAx[k],     tya = TAy[k];
            float txb = TAx[k + 1], tyb = TAy[k + 1];
            float fr = txa * G0.x - tya * G0.y + txb * G1.x - tyb * G1.y;
            float fi = txa * G0.y + tya * G0.x + txb * G1.y + tyb * G1.x;
            float nr = fr + L.x * zr - L.y * zi;
            float ni = fi + L.x * zi + L.y * zr;
            zr = nr; zi = ni;
        }
        zloc[c][l] = make_float2(zr, zi);
        __syncthreads();

        if (c == 0) {
            float2 base = L, pw = make_float2(1.0f, 0.0f);
            int ee = CLM;
            while (ee) { if (ee & 1) pw = cmulf(pw, base); base = cmulf(base, base); ee >>= 1; }

            float kr = 0.0f, ki = 0.0f;
            carr[0][l] = make_float2(0.0f, 0.0f);
            for (int cc = 0; cc < NCHM - 1; ++cc) {
                float2 sv = zloc[cc][l];
                float nr = pw.x * kr - pw.y * ki + sv.x;
                float ni = pw.x * ki + pw.y * kr + sv.y;
                kr = nr; ki = ni;
                carr[cc + 1][l] = make_float2(kr, ki);
            }
        }
        __syncthreads();

        float2 K = carr[c][l];
        zr = K.x; zi = K.y;
        for (int m = 0; m < len; ++m) {
            const int k = k0 + m;
            float txa = TAx[k],     tya = TAy[k];
            float txb = TAx[k + 1], tyb = TAy[k + 1];
            float fr = txa * G0.x - tya * G0.y + txb * G1.x - tyb * G1.y;
            float fi = txa * G0.y + tya * G0.x + txb * G1.y + tyb * G1.x;
            float nr = fr + L.x * zr - L.y * zi;
            float ni = fi + L.x * zi + L.y * zr;
            zr = nr; zi = ni;
            g_Z[(k + 1) * NL + l] = make_float2(zr, zi);
        }
        __syncthreads();
        __threadfence();
        if (tid == 0) atomicAdd(&g_flag, 1u);
    }
    // =======================================================================
    // Phase T (blocks 1..45): transform 16 timesteps each
    // =======================================================================
    else {
        if (tid == 0)
            while (atomicAdd(&g_flag, 0u) < e) __nanosleep(32);
        __syncthreads();
        __threadfence();

        for (int i = tid; i < NL * NL; i += TBLK) As[i] = g_A[i];

        const int kbase = (b - 1) * 16;
        for (int i = tid; i < 16 * NL; i += TBLK) {
            int kk = i >> 5, li = i & 31;
            int k = kbase + kk;
            Zs[i] = (k >= 1 && k < NF) ? g_Z[k * NL + li] : make_float2(0.0f, 0.0f);
        }
        __syncthreads();

        const int kk = tid >> 5, r = tid & 31;
        const int k  = kbase + kk;
        if (k < NF) {
            const u64* zv = reinterpret_cast<const u64*>(&Zs[kk * NL]);
            u64 acc = 0ull;
            #pragma unroll
            for (int li = 0; li < NL; ++li) {
                float a = As[li * NL + r];
                ffma2(acc, pk2(a, a), zv[li]);
            }
            float u, v;
            upk2(u, v, acc);
            out[k * NL + r]           = u;
            out[NF * NL + k * NL + r] = v;
        }
    }
}

extern "C" void kernel_launch(void* const* d_in, const int* in_sizes, int n_in,
                              void* d_out, int out_size)
{
    const float* pk  = (const float*)d_in[0];
    const float* TAx = (const float*)d_in[1];
    const float* TAy = (const float*)d_in[2];
    const float* fc  = (const float*)d_in[3];
    float* out = (float*)d_out;

    mega_kernel<<<GRID1, TBLK>>>(pk, fc, TAx, TAy, out);
}

// round 14
// speedup vs baseline: 1.3053x; 1.3053x over previous
#include <cuda_runtime.h>

#define NL     32
#define NF     720
#define DTF    60.0f
#define SCALE  256.0f
#define CLM    45          // modal chunk length (16 warps: 15*45 + 44 = 719)
#define NCHM   16
#define TBLK   512
#define GRID2  46          // block 0 = modal, blocks 1..45 = transform

typedef unsigned long long u64;
#define FULL 0xffffffffu

// Persistent scratch
__device__ float    g_A  [NL * NL];   // A[l*32+r] = Q[r][l] / d_r
__device__ float2   g_Lam[NL];
__device__ float2   g_G0u[NL];        // unscaled forcing coeffs
__device__ float2   g_G1u[NL];
__device__ float    g_sc [NL];        // per-mode forcing scale (DT*Kin0*v0)
__device__ float2   g_Z  [NF * NL];
__device__ unsigned g_flag;

// ---- packed f32x2 helpers ---------------------------------------------------
__device__ __forceinline__ u64 pk2(float lo, float hi) {
    u64 r; asm("mov.b64 %0, {%1, %2};" : "=l"(r) : "f"(lo), "f"(hi)); return r;
}
__device__ __forceinline__ void upk2(float& lo, float& hi, u64 v) {
    asm("mov.b64 {%0, %1}, %2;" : "=f"(lo), "=f"(hi) : "l"(v));
}
__device__ __forceinline__ void ffma2(u64& d, u64 a, u64 b) {
    asm("fma.rn.f32x2 %0, %1, %2, %3;" : "=l"(d) : "l"(a), "l"(b), "l"(d));
}
__device__ __forceinline__ float frcpa(float x) {
    float r; asm("rcp.approx.f32 %0, %1;" : "=f"(r) : "f"(x)); return r;
}
__device__ __forceinline__ float2 cmulf(float2 a, float2 b) {
    return make_float2(a.x * b.x - a.y * b.y, a.x * b.y + a.y * b.x);
}

// Sturm count with 4-step batched rescaling (sign-preserving: sc > 0).
__device__ __forceinline__ int sturm_count(float x,
                                           const float* __restrict__ ch,
                                           const float* __restrict__ s2h)
{
    float p0 = 1.0f;
    float p1 = ch[0] - x;
    bool  s1 = (p1 < 0.0f) || (p1 == 0.0f);
    int   cnt = s1 ? 1 : 0;
    #pragma unroll
    for (int r = 1; r < NL; ++r) {
        float p2 = fmaf(ch[r] - x, p1, -s2h[r] * p0);
        bool sg = (p2 < 0.0f);
        if (p2 == 0.0f) sg = !s1;
        cnt += (sg != s1) ? 1 : 0;
        p0 = p1; p1 = p2; s1 = sg;
        if ((r & 3) == 3) {       // batch rescale: positive factor, signs kept
            float m  = fmaxf(fmaxf(fabsf(p0), fabsf(p1)), 1e-30f);
            float sc = frcpa(m);
            p0 *= sc; p1 *= sc;
        }
    }
    return cnt;
}

// ---------------------------------------------------------------------------
// Kernel 1: eigen solve. 32 blocks x 64 threads (2 warps).
//   both warps : bisection (redundant, parallel)
//   warp 0     : Thomas inverse iteration -> eigenvector, g_A, g_sc
//   warp 1     : closed-form fp64 constants -> g_Lam, g_G0u, g_G1u
// ---------------------------------------------------------------------------
__global__ void __launch_bounds__(64, 1)
eigen_kernel(const float* __restrict__ pk, const float* __restrict__ fc)
{
    __shared__ float ch [NL];
    __shared__ float sh [NL];
    __shared__ float s2h[NL];
    __shared__ float vsm[NL];

    const int tid  = threadIdx.x;
    const int lane = tid & 31;
    const int w    = tid >> 5;
    const int l    = blockIdx.x;

    if (l == 0 && tid == 0) g_flag = 0;      // reset main2 rendezvous

    float dinv = 0.0f;
    if (w == 0) {
        const float kin  = expf(pk[2 * lane]);
        const float kout = expf(pk[2 * lane + 1]);
        // symmetrizer prefix
        float t = (lane > 0) ? 0.5f * (pk[2 * lane - 1] - pk[2 * lane]) : 0.0f;
        #pragma unroll
        for (int o = 1; o < 32; o <<= 1) {
            float u = __shfl_up_sync(FULL, t, o);
            if (lane >= o) t += u;
        }
        dinv = expf(-t);

        const float c = -DTF * (((lane > 0) ? kin : 0.0f) + kout) * SCALE;
        const float s = (lane > 0)
            ? DTF * expf(0.5f * (pk[2 * lane] + pk[2 * lane - 1])) * SCALE
            : 0.0f;
        ch[lane]  = c;
        sh[lane]  = s;
        s2h[lane] = s * s;
    }
    __syncthreads();

    // ---- bisection (both warps, identical result) ----
    const float c_  = ch[lane];
    const float s_  = sh[lane];
    const float op_ = (lane < NL - 1) ? sh[lane + 1] : 0.0f;
    float rad = s_ + op_;
    float lo  = c_ - rad, hi = c_ + rad;
    #pragma unroll
    for (int o = 16; o > 0; o >>= 1) {
        lo = fminf(lo, __shfl_xor_sync(FULL, lo, o));
        hi = fmaxf(hi, __shfl_xor_sync(FULL, hi, o));
    }
    float width = hi - lo;
    float a_ = lo - 1e-6f * (fabsf(width) + 1.0f);
    float b_ = hi + 1e-6f * (fabsf(width) + 1.0f);

    for (int round = 0; round < 5; ++round) {
        float x = a_ + (b_ - a_) * (float)(lane + 1) * (1.0f / 33.0f);
        int cnt = sturm_count(x, ch, s2h);
        unsigned mask = __ballot_sync(FULL, cnt <= l);
        if (mask) {
            int j = 31 - __clz((int)mask);
            float na = __shfl_sync(FULL, x, j);
            float nb = (j < 31) ? __shfl_sync(FULL, x, j + 1) : b_;
            a_ = na; b_ = nb;
        } else {
            b_ = __shfl_sync(FULL, x, 0);
        }
    }
    const float xhat = 0.5f * (a_ + b_);

    if (w == 0) {
        // ---- Thomas inverse iteration (lane 0), 2 sweeps + inf-norm guard ----
        if (lane == 0) {
            float rp[NL];
            {
                float dd = ch[0] - xhat;
                dd = copysignf(fmaxf(fabsf(dd), 1e-12f), dd);
                rp[0] = frcpa(dd);
                #pragma unroll
                for (int r = 1; r < NL; ++r) {
                    dd = fmaf(-s2h[r], rp[r - 1], ch[r] - xhat);
                    dd = copysignf(fmaxf(fabsf(dd), 1e-12f), dd);
                    rp[r] = frcpa(dd);
                }
            }
            float vb[NL];
            #pragma unroll
            for (int r = 0; r < NL; ++r) vb[r] = 1.0f;

            #pragma unroll
            for (int it = 0; it < 2; ++it) {
                float wk[NL];
                wk[0] = vb[0];
                #pragma unroll
                for (int r = 1; r < NL; ++r)
                    wk[r] = fmaf(-sh[r] * rp[r - 1], wk[r - 1], vb[r]);
                wk[NL - 1] = wk[NL - 1] * rp[NL - 1];
                #pragma unroll
                for (int r = NL - 2; r >= 0; --r)
                    wk[r] = (wk[r] - sh[r + 1] * wk[r + 1]) * rp[r];

                // cheap overflow guard between sweeps (inf-norm rescale)
                float m = 1e-30f;
                #pragma unroll
                for (int r = 0; r < NL; ++r) m = fmaxf(m, fabsf(wk[r]));
                float im = frcpa(m);
                #pragma unroll
                for (int r = 0; r < NL; ++r) vb[r] = wk[r] * im;
            }
            #pragma unroll
            for (int r = 0; r < NL; ++r) vsm[r] = vb[r];
        }
        __syncwarp();

        // lane-parallel final normalization + outputs
        float v  = vsm[lane];
        float n2 = v * v;
        #pragma unroll
        for (int o = 16; o > 0; o >>= 1) n2 += __shfl_xor_sync(FULL, n2, o);
        float inv = rsqrtf(n2);
        g_A[l * NL + lane] = v * inv * dinv;
        float v0n = __shfl_sync(FULL, v, 0) * inv;
        if (lane == 0) g_sc[l] = DTF * expf(pk[0]) * v0n;
    } else if (lane == 0) {
        // ---- closed-form fp64 constants ----
        const double mur = (double)xhat * (1.0 / (double)SCALE);
        const double mui = -(double)DTF * (double)fc[0];
        const double br  = 1.0 + mur, bi = mui;

        // beta^2, ^4, ^8, ^16, ^32
        double b2r  = br * br - bi * bi,     b2i  = 2.0 * br * bi;
        double b4r  = b2r * b2r - b2i * b2i, b4i  = 2.0 * b2r * b2i;
        double b8r  = b4r * b4r - b4i * b4i, b8i  = 2.0 * b4r * b4i;
        double b16r = b8r * b8r - b8i * b8i, b16i = 2.0 * b8r * b8i;
        double b32r = b16r * b16r - b16i * b16i, b32i = 2.0 * b16r * b16i;

        // Lambda = beta^60 = b32*b16*b8*b4
        double Lr = b32r * b16r - b32i * b16i;
        double Li = b32r * b16i + b32i * b16r;
        { double tr = Lr * b8r - Li * b8i; Li = Lr * b8i + Li * b8r; Lr = tr; }
        { double tr = Lr * b4r - Li * b4i; Li = Lr * b4i + Li * b4r; Lr = tr; }

        // G0 = (1 - L + 60*mu*L)/(60 mu^2),  G1 = (L - 1 - 60*mu)/(60 mu^2)
        double mLr = mur * Lr - mui * Li;
        double mLi = mur * Li + mui * Lr;
        double n0r = 1.0 - Lr + 60.0 * mLr, n0i = -Li + 60.0 * mLi;
        double n1r = Lr - 1.0 - 60.0 * mur, n1i = Li - 60.0 * mui;
        double m2r = mur * mur - mui * mui, m2i = 2.0 * mur * mui;
        double dr  = 60.0 * m2r, di = 60.0 * m2i;
        double idn = 1.0 / (dr * dr + di * di);
        double G0r = (n0r * dr + n0i * di) * idn;
        double G0i = (n0i * dr - n0r * di) * idn;
        double G1r = (n1r * dr + n1i * di) * idn;
        double G1i = (n1i * dr - n1r * di) * idn;

        g_Lam[l] = make_float2((float)Lr,  (float)Li);
        g_G0u[l] = make_float2((float)G0r, (float)G0i);
        g_G1u[l] = make_float2((float)G1r, (float)G1i);
    }
}

// ---------------------------------------------------------------------------
// Kernel 2: fused modal + transform (R12 structure, unchanged numerics).
// ---------------------------------------------------------------------------
__global__ void __launch_bounds__(TBLK, 1)
main2_kernel(const float* __restrict__ TAx, const float* __restrict__ TAy,
             float* __restrict__ out)
{
    const int tid = threadIdx.x;

    if (blockIdx.x == 0) {
        __shared__ float2 zloc[NCHM][NL];
        __shared__ float2 carr[NCHM][NL];

        const int l = tid & 31;
        const int c = tid >> 5;

        const float2 L  = g_Lam[l];
        const float  sc = g_sc[l];
        float2 G0 = g_G0u[l]; G0.x *= sc; G0.y *= sc;
        float2 G1 = g_G1u[l]; G1.x *= sc; G1.y *= sc;

        const int k0  = c * CLM;
        const int len = min(CLM, (NF - 1) - k0);

        float zr = 0.0f, zi = 0.0f;
        for (int m = 0; m < len; ++m) {
            const int k = k0 + m;
            float txa = TAx[k],     tya = TAy[k];
            float txb = TAx[k + 1], tyb = TAy[k + 1];
            float fr = txa * G0.x - tya * G0.y + txb * G1.x - tyb * G1.y;
            float fi = txa * G0.y + tya * G0.x + txb * G1.y + tyb * G1.x;
            float nr = fr + L.x * zr - L.y * zi;
            float ni = fi + L.x * zi + L.y * zr;
            zr = nr; zi = ni;
        }
        zloc[c][l] = make_float2(zr, zi);
        __syncthreads();

        if (c == 0) {
            float2 base = L, pw = make_float2(1.0f, 0.0f);
            int e = CLM;
            while (e) { if (e & 1) pw = cmulf(pw, base); base = cmulf(base, base); e >>= 1; }

            float kr = 0.0f, ki = 0.0f;
            carr[0][l] = make_float2(0.0f, 0.0f);
            for (int cc = 0; cc < NCHM - 1; ++cc) {
                float2 sv = zloc[cc][l];
                float nr = pw.x * kr - pw.y * ki + sv.x;
                float ni = pw.x * ki + pw.y * kr + sv.y;
                kr = nr; ki = ni;
                carr[cc + 1][l] = make_float2(kr, ki);
            }
        }
        __syncthreads();

        float2 K = carr[c][l];
        zr = K.x; zi = K.y;
        for (int m = 0; m < len; ++m) {
            const int k = k0 + m;
            float txa = TAx[k],     tya = TAy[k];
            float txb = TAx[k + 1], tyb = TAy[k + 1];
            float fr = txa * G0.x - tya * G0.y + txb * G1.x - tyb * G1.y;
            float fi = txa * G0.y + tya * G0.x + txb * G1.y + tyb * G1.x;
            float nr = fr + L.x * zr - L.y * zi;
            float ni = fi + L.x * zi + L.y * zr;
            zr = nr; zi = ni;
            g_Z[(k + 1) * NL + l] = make_float2(zr, zi);
        }
        __syncthreads();
        __threadfence();
        if (tid == 0) atomicExch(&g_flag, 1);
    } else {
        __shared__ float  As[NL * NL];
        __shared__ float2 Zs[16 * NL];

        for (int i = tid; i < NL * NL; i += TBLK) As[i] = g_A[i];

        if (tid == 0)
            while (atomicAdd(&g_flag, 0) == 0) __nanosleep(32);
        __syncthreads();
        __threadfence();

        const int kbase = (blockIdx.x - 1) * 16;
        for (int i = tid; i < 16 * NL; i += TBLK) {
            int kk = i >> 5, li = i & 31;
            int k = kbase + kk;
            Zs[i] = (k >= 1 && k < NF) ? g_Z[k * NL + li] : make_float2(0.0f, 0.0f);
        }
        __syncthreads();

        const int kk = tid >> 5, r = tid & 31;
        const int k  = kbase + kk;
        if (k >= NF) return;

        const u64* zv = reinterpret_cast<const u64*>(&Zs[kk * NL]);
        u64 acc = 0ull;
        #pragma unroll
        for (int li = 0; li < NL; ++li) {
            float a = As[li * NL + r];
            ffma2(acc, pk2(a, a), zv[li]);
        }
        float u, v;
        upk2(u, v, acc);
        out[k * NL + r]           = u;
        out[NF * NL + k * NL + r] = v;
    }
}

extern "C" void kernel_launch(void* const* d_in, const int* in_sizes, int n_in,
                              void* d_out, int out_size)
{
    const float* pk  = (const float*)d_in[0];
    const float* TAx = (const float*)d_in[1];
    const float* TAy = (const float*)d_in[2];
    const float* fc  = (const float*)d_in[3];
    float* out = (float*)d_out;

    eigen_kernel<<<NL, 64>>>(pk, fc);
    main2_kernel<<<GRID2, TBLK>>>(TAx, TAy, out);
}